// round 9
// baseline (speedup 1.0000x reference)
#include <cuda_runtime.h>

#define BATCH  8
#define NPTS   4096
#define TPB    64
#define QPT    4
#define QPB    (TPB * QPT)       // 256 queries per block
#define ITILES (NPTS / QPB)      // 16
#define NSPLIT 8                 // target splits
#define CHUNK  (NPTS / NSPLIT)   // 512 targets per block (one 8KB smem tile)
#define NQ     (2 * BATCH * NPTS)            // 65536 queries
#define NBLK   (ITILES * BATCH * 2 * NSPLIT) // 2048 blocks x 2 warps

// bits of -(min d2) per query, signed-int atomicMin.
// int-min of bits(-v) == bits(-(float-min of v)) for the values seen here.
// .bss zero (= +0.0 bits) is the identity; finisher re-zeros for replay.
__device__ __align__(16) int g_minneg[NQ];
__device__ unsigned int      g_count;     // zero-init; finisher resets

// ---- packed f32x2 helpers (Blackwell; PTX-only) ----
__device__ __forceinline__ unsigned long long bcast2(float v) {
    unsigned long long r;
    asm("mov.b64 %0, {%1, %1};" : "=l"(r) : "f"(v));
    return r;
}
__device__ __forceinline__ unsigned long long fma2(unsigned long long a,
                                                   unsigned long long b,
                                                   unsigned long long c) {
    unsigned long long d;
    asm("fma.rn.f32x2 %0, %1, %2, %3;" : "=l"(d) : "l"(a), "l"(b), "l"(c));
    return d;
}
__device__ __forceinline__ void unpack2(unsigned long long v, float& lo, float& hi) {
    asm("mov.b64 {%0, %1}, %2;" : "=f"(lo), "=f"(hi) : "l"(v));
}

// grid (ITILES, BATCH, 2*NSPLIT); z: dir = z&1, split = z>>1.
// 2048 narrow blocks (2 warps) -> ~14 blocks/SM; prologues/tails overlap
// across blocks. Each thread: 4 queries x 512 targets via one smem tile.
__global__ __launch_bounds__(TPB, 14) void chamfer_kernel(
    const float* __restrict__ A, const float* __restrict__ Bp,
    float* __restrict__ out)
{
    const int dir   = blockIdx.z & 1;
    const int split = blockIdx.z >> 1;
    const int b     = blockIdx.y;
    const float* __restrict__ xb = (dir == 0 ? A : Bp) + (size_t)b * NPTS * 3;
    const float* __restrict__ yb = (dir == 0 ? Bp : A) + (size_t)b * NPTS * 3;

    __shared__ __align__(16) float xs[CHUNK], ys[CHUNK], zs[CHUNK], ws[CHUNK];

    // ---- query-point LDGs first (overlap with tile fill + barrier) ----
    const int iBase = blockIdx.x * QPB + threadIdx.x;
    float qpx[QPT], qpy[QPT], qpz[QPT];
    #pragma unroll
    for (int q = 0; q < QPT; q++) {
        const int i = iBase + q * TPB;
        qpx[q] = xb[3 * i + 0];
        qpy[q] = xb[3 * i + 1];
        qpz[q] = xb[3 * i + 2];
    }

    // ---- tile fill: 512 targets by 64 threads ----
    const int t0 = split * CHUNK;
    #pragma unroll
    for (int k = threadIdx.x; k < CHUNK; k += TPB) {
        const float tx = yb[3 * (t0 + k) + 0];
        const float ty = yb[3 * (t0 + k) + 1];
        const float tz = yb[3 * (t0 + k) + 2];
        xs[k] = tx; ys[k] = ty; zs[k] = tz;
        ws[k] = fmaf(tx, tx, fmaf(ty, ty, tz * tz));
    }

    // ---- fold -2 into packed broadcasts ----
    float p2[QPT];
    unsigned long long nx[QPT], ny[QPT], nz[QPT];
    #pragma unroll
    for (int q = 0; q < QPT; q++) {
        p2[q] = fmaf(qpx[q], qpx[q], fmaf(qpy[q], qpy[q], qpz[q] * qpz[q]));
        nx[q] = bcast2(-2.0f * qpx[q]);
        ny[q] = bcast2(-2.0f * qpy[q]);
        nz[q] = bcast2(-2.0f * qpz[q]);
    }

    __syncthreads();

    float m0[QPT], m1[QPT], m2[QPT], m3[QPT];
    #pragma unroll
    for (int q = 0; q < QPT; q++) { m0[q] = m1[q] = m2[q] = m3[q] = 3.0e38f; }

    const ulonglong2* __restrict__ X4 = (const ulonglong2*)xs;
    const ulonglong2* __restrict__ Y4 = (const ulonglong2*)ys;
    const ulonglong2* __restrict__ Z4 = (const ulonglong2*)zs;
    const ulonglong2* __restrict__ W4 = (const ulonglong2*)ws;

    #pragma unroll 4
    for (int j = 0; j < CHUNK / 4; j++) {
        const ulonglong2 xv = X4[j];   // {x0,x1},{x2,x3} packed f32x2 (broadcast)
        const ulonglong2 yv = Y4[j];
        const ulonglong2 zv = Z4[j];
        const ulonglong2 wv = W4[j];

        #pragma unroll
        for (int q = 0; q < QPT; q++) {
            const unsigned long long t01 =
                fma2(nx[q], xv.x, fma2(ny[q], yv.x, fma2(nz[q], zv.x, wv.x)));
            const unsigned long long t23 =
                fma2(nx[q], xv.y, fma2(ny[q], yv.y, fma2(nz[q], zv.y, wv.y)));
            float u0, u1, u2, u3;
            unpack2(t01, u0, u1); unpack2(t23, u2, u3);
            m0[q] = fminf(m0[q], u0); m1[q] = fminf(m1[q], u1);
            m2[q] = fminf(m2[q], u2); m3[q] = fminf(m3[q], u3);
        }
    }

    const int qbase = (dir * BATCH + b) * NPTS;
    #pragma unroll
    for (int q = 0; q < QPT; q++) {
        const float v = p2[q] + fminf(fminf(m0[q], m1[q]), fminf(m2[q], m3[q]));
        atomicMin(&g_minneg[qbase + iBase + q * TPB], __float_as_int(-v));
    }

    // ---- last-block finisher (deterministic, self-resetting) ----
    __threadfence();           // order this block's REDGs before the counter
    __syncthreads();
    __shared__ unsigned int s_rank;
    if (threadIdx.x == 0) s_rank = atomicAdd(&g_count, 1u);
    __syncthreads();
    if (s_rank != NBLK - 1) return;

    __threadfence();           // acquire: all blocks' REDG results visible

    float s = 0.0f;
    int4* __restrict__ P = (int4*)g_minneg;
    #pragma unroll 8
    for (int k = 0; k < NQ / 4 / TPB; k++) {          // 256 int4 per thread
        const int idx = threadIdx.x + k * TPB;
        const int4 v = P[idx];
        s += fmaxf(-__int_as_float(v.x), 0.0f)
           + fmaxf(-__int_as_float(v.y), 0.0f)
           + fmaxf(-__int_as_float(v.z), 0.0f)
           + fmaxf(-__int_as_float(v.w), 0.0f);
        P[idx] = make_int4(0, 0, 0, 0);               // restore identity for replay
    }

    #pragma unroll
    for (int o = 16; o > 0; o >>= 1)
        s += __shfl_down_sync(0xffffffffu, s, o);

    __shared__ float wsum[TPB / 32];
    if ((threadIdx.x & 31) == 0) wsum[threadIdx.x >> 5] = s;
    __syncthreads();
    if (threadIdx.x == 0) {
        float tot = 0.0f;
        #pragma unroll
        for (int w = 0; w < TPB / 32; w++) tot += wsum[w];
        out[0] = tot / (float)(BATCH * NPTS);
        g_count = 0;                                   // reset for next replay
    }
}

extern "C" void kernel_launch(void* const* d_in, const int* in_sizes, int n_in,
                              void* d_out, int out_size)
{
    const float* A  = (const float*)d_in[0];  // coor_recon [8,4096,3]
    const float* Bp = (const float*)d_in[1];  // pc_gd      [8,4096,3]
    float* out = (float*)d_out;

    dim3 grid(ITILES, BATCH, 2 * NSPLIT);     // 2048 blocks, single launch
    chamfer_kernel<<<grid, TPB>>>(A, Bp, out);
}

// round 10
// speedup vs baseline: 1.2621x; 1.2621x over previous
#include <cuda_runtime.h>

#define BATCH  8
#define NPTS   4096
#define TPB    64
#define QPT    4
#define QPB    (TPB * QPT)       // 256 queries per block
#define ITILES (NPTS / QPB)      // 16
#define NSPLIT 8                 // target splits
#define CHUNK  (NPTS / NSPLIT)   // 512 targets per block (one 8KB smem tile)
#define NQ     (2 * BATCH * NPTS)            // 65536 queries
#define SBLK   64
#define STPB   256

// bits of -(min d2) per query, signed-int atomicMin.
// int-min of bits(-v) == bits(-(float-max of -v)) == min d2 for these values.
// .bss zero (= +0.0 bits) is the identity: any negative int wins. No init kernel.
// sum_kernel re-zeros slots after reading, restoring state for graph replay.
__device__ __align__(16) int g_minneg[NQ];
__device__ float             g_cpart[SBLK];
__device__ unsigned int      g_count;        // zero-init; sum_kernel resets

// ---- packed f32x2 helpers (Blackwell; PTX-only) ----
__device__ __forceinline__ unsigned long long bcast2(float v) {
    unsigned long long r;
    asm("mov.b64 %0, {%1, %1};" : "=l"(r) : "f"(v));
    return r;
}
__device__ __forceinline__ unsigned long long fma2(unsigned long long a,
                                                   unsigned long long b,
                                                   unsigned long long c) {
    unsigned long long d;
    asm("fma.rn.f32x2 %0, %1, %2, %3;" : "=l"(d) : "l"(a), "l"(b), "l"(c));
    return d;
}
__device__ __forceinline__ void unpack2(unsigned long long v, float& lo, float& hi) {
    asm("mov.b64 {%0, %1}, %2;" : "=f"(lo), "=f"(hi) : "l"(v));
}

// grid (ITILES, BATCH, 2*NSPLIT); z: dir = z&1, split = z>>1.
// NO gpu-scope fence anywhere in this kernel: __threadfence flushes L1D
// (CCTL.IVALL) and thrashes co-resident blocks — measured +25% in R6-R9.
__global__ __launch_bounds__(TPB) void chamfer_kernel(
    const float* __restrict__ A, const float* __restrict__ Bp)
{
    const int dir   = blockIdx.z & 1;
    const int split = blockIdx.z >> 1;
    const int b     = blockIdx.y;
    const float* __restrict__ xb = (dir == 0 ? A : Bp) + (size_t)b * NPTS * 3;
    const float* __restrict__ yb = (dir == 0 ? Bp : A) + (size_t)b * NPTS * 3;

    __shared__ __align__(16) float xs[CHUNK], ys[CHUNK], zs[CHUNK], ws[CHUNK];

    // ---- load the target tile (once per block) ----
    const int t0 = split * CHUNK;
    #pragma unroll
    for (int k = threadIdx.x; k < CHUNK; k += TPB) {
        const float qx = yb[3 * (t0 + k) + 0];
        const float qy = yb[3 * (t0 + k) + 1];
        const float qz = yb[3 * (t0 + k) + 2];
        xs[k] = qx; ys[k] = qy; zs[k] = qz;
        ws[k] = fmaf(qx, qx, fmaf(qy, qy, qz * qz));
    }

    // ---- load 4 query points, fold -2 into packed broadcasts ----
    const int iBase = blockIdx.x * QPB + threadIdx.x;
    float p2[QPT];
    unsigned long long nx[QPT], ny[QPT], nz[QPT];
    #pragma unroll
    for (int q = 0; q < QPT; q++) {
        const int i = iBase + q * TPB;
        const float px = xb[3 * i + 0];
        const float py = xb[3 * i + 1];
        const float pz = xb[3 * i + 2];
        p2[q] = fmaf(px, px, fmaf(py, py, pz * pz));
        nx[q] = bcast2(-2.0f * px);
        ny[q] = bcast2(-2.0f * py);
        nz[q] = bcast2(-2.0f * pz);
    }

    __syncthreads();

    float m0[QPT], m1[QPT], m2[QPT], m3[QPT];
    #pragma unroll
    for (int q = 0; q < QPT; q++) { m0[q] = m1[q] = m2[q] = m3[q] = 3.0e38f; }

    const ulonglong2* __restrict__ X4 = (const ulonglong2*)xs;
    const ulonglong2* __restrict__ Y4 = (const ulonglong2*)ys;
    const ulonglong2* __restrict__ Z4 = (const ulonglong2*)zs;
    const ulonglong2* __restrict__ W4 = (const ulonglong2*)ws;

    #pragma unroll 4
    for (int j = 0; j < CHUNK / 4; j++) {
        const ulonglong2 xv = X4[j];   // {x0,x1},{x2,x3} packed f32x2 (broadcast)
        const ulonglong2 yv = Y4[j];
        const ulonglong2 zv = Z4[j];
        const ulonglong2 wv = W4[j];

        #pragma unroll
        for (int q = 0; q < QPT; q++) {
            const unsigned long long t01 =
                fma2(nx[q], xv.x, fma2(ny[q], yv.x, fma2(nz[q], zv.x, wv.x)));
            const unsigned long long t23 =
                fma2(nx[q], xv.y, fma2(ny[q], yv.y, fma2(nz[q], zv.y, wv.y)));
            float u0, u1, u2, u3;
            unpack2(t01, u0, u1); unpack2(t23, u2, u3);
            m0[q] = fminf(m0[q], u0); m1[q] = fminf(m1[q], u1);
            m2[q] = fminf(m2[q], u2); m3[q] = fminf(m3[q], u3);
        }
    }

    const int qbase = (dir * BATCH + b) * NPTS;
    #pragma unroll
    for (int q = 0; q < QPT; q++) {
        const float v = p2[q] + fminf(fminf(m0[q], m1[q]), fminf(m2[q], m3[q]));
        atomicMin(&g_minneg[qbase + iBase + q * TPB], __float_as_int(-v));
    }
    // fire-and-forget REDG.MIN; kernel boundary orders them before sum_kernel
}

// Clamp + deterministic mean; re-zeros g_minneg for the next graph replay.
__global__ __launch_bounds__(STPB) void sum_kernel(float* __restrict__ out)
{
    const int t = blockIdx.x * STPB + threadIdx.x;       // 16384 threads
    int4* __restrict__ P = (int4*)g_minneg;
    const int4 v = P[t];
    P[t] = make_int4(0, 0, 0, 0);                        // restore identity
    float s = fmaxf(-__int_as_float(v.x), 0.0f)
            + fmaxf(-__int_as_float(v.y), 0.0f)
            + fmaxf(-__int_as_float(v.z), 0.0f)
            + fmaxf(-__int_as_float(v.w), 0.0f);

    #pragma unroll
    for (int o = 16; o > 0; o >>= 1)
        s += __shfl_down_sync(0xffffffffu, s, o);

    __shared__ float wsum[STPB / 32];
    __shared__ int   is_last;
    if ((threadIdx.x & 31) == 0) wsum[threadIdx.x >> 5] = s;
    __syncthreads();

    if (threadIdx.x == 0) {
        float ps = 0.0f;
        #pragma unroll
        for (int w = 0; w < STPB / 32; w++) ps += wsum[w];
        g_cpart[blockIdx.x] = ps;
        __threadfence();
        unsigned int old = atomicAdd(&g_count, 1u);
        is_last = (old == SBLK - 1) ? 1 : 0;
    }
    __syncthreads();

    if (is_last && threadIdx.x < 32) {
        float v2 = g_cpart[threadIdx.x] + g_cpart[threadIdx.x + 32];
        #pragma unroll
        for (int o = 16; o > 0; o >>= 1)
            v2 += __shfl_down_sync(0xffffffffu, v2, o);
        if (threadIdx.x == 0) {
            out[0] = v2 / (float)(BATCH * NPTS);
            g_count = 0;                                  // reset for next replay
        }
    }
}

extern "C" void kernel_launch(void* const* d_in, const int* in_sizes, int n_in,
                              void* d_out, int out_size)
{
    const float* A  = (const float*)d_in[0];  // coor_recon [8,4096,3]
    const float* Bp = (const float*)d_in[1];  // pc_gd      [8,4096,3]
    float* out = (float*)d_out;

    dim3 grid(ITILES, BATCH, 2 * NSPLIT);     // 2048 blocks
    chamfer_kernel<<<grid, TPB>>>(A, Bp);
    sum_kernel<<<SBLK, STPB>>>(out);
}